// round 9
// baseline (speedup 1.0000x reference)
#include <cuda_runtime.h>
#include <cuda.h>

#define SQ   1024
#define BS   64
#define HD   512
#define ED   256
#define VB   32000
#define G3   1536
#define EOSV 2
#define NEOS 32

#define NBG  4            // batch groups (16 rows each)
#define NRG  32           // j groups (16 h-dims each)
#define NCTA (NBG*NRG)    // 128 persistent CTAs
#define CLU  8            // cluster size (same-bg CTAs sharing h via multicast)

#define PSTR 26           // psum row stride (floats): 8B-aligned, bank-clean
// dynamic smem: h tile 32KB + psum + mbar(16B)
#define SM_H_BYTES    (16*HD*4)                 // 32768
#define SM_PSUM_BYTES (16*16*PSTR*4)            // 26624
#define GRU_SMEM      (SM_H_BYTES + SM_PSUM_BYTES + 16)

#define H_TILE_BYTES  (16*HD*4)                 // 32768 per bg
#define SLICE_ROWS    4                          // 32 rows / 8 ranks
#define SLICE_BYTES   (SLICE_ROWS*256*4)         // 4096

typedef unsigned long long u64;

// ------------------- device scratch (static only; no allocs) ----------------
__device__ float    g_Gtab[(size_t)VB * G3];   // ~197MB input-projection table
__device__ float    g_h[2][BS * HD];           // double-buffered hidden state
__device__ int      g_dest[SQ * BS];           // EOS compaction slot or -1
__device__ unsigned g_ctr[NBG * 64];           // barrier counters, 256B stride

// ------------------- packed f32x2 helpers ----------------------------------
__device__ __forceinline__ u64 ffma2(u64 a, u64 b, u64 c) {
    u64 d;
    asm("fma.rn.f32x2 %0, %1, %2, %3;" : "=l"(d) : "l"(a), "l"(b), "l"(c));
    return d;
}
__device__ __forceinline__ float2 unpack2(u64 v) {
    float2 f;
    asm("mov.b64 {%0, %1}, %2;" : "=f"(f.x), "=f"(f.y) : "l"(v));
    return f;
}
__device__ __forceinline__ float hsum2(u64 v) {
    float2 f = unpack2(v);
    return f.x + f.y;
}
__device__ __forceinline__ u64 bcast2(float x) {
    u64 d;
    asm("mov.b64 %0, {%1, %1};" : "=l"(d) : "f"(x));
    return d;
}
__device__ __forceinline__ unsigned ld_acq(const unsigned* p) {
    unsigned v;
    asm volatile("ld.acquire.gpu.global.u32 %0, [%1];" : "=r"(v) : "l"(p));
    return v;
}
__device__ __forceinline__ void red_release_add(unsigned* p, unsigned v) {
    asm volatile("red.release.gpu.global.add.u32 [%0], %1;" :: "l"(p), "r"(v) : "memory");
}
__device__ __forceinline__ unsigned smem_u32(const void* p) {
    unsigned a;
    asm("{ .reg .u64 t; cvta.to.shared.u64 t, %1; cvt.u32.u64 %0, t; }"
        : "=r"(a) : "l"(p));
    return a;
}

// ------------------- Gtab GEMM (+fused prep): G = w_ih * emb^T + b_ih ------
__global__ void __launch_bounds__(256) gtab_kernel(
    const float* __restrict__ emb,
    const float* __restrict__ w_ih,
    const float* __restrict__ b_ih,
    const int*   __restrict__ tokens)
{
    // ---- fused prep: h0, counters, EOS scan (first 64 flat CTAs, warp 0) ----
    int fid = blockIdx.y * 12 + blockIdx.x;
    if (fid < BS && threadIdx.x < 32) {
        int b = fid, t = threadIdx.x;
        if (fid == 0 && t < NBG) g_ctr[t * 64] = 0u;
        for (int i = t; i < HD; i += 32) g_h[0][b * HD + i] = 0.f;
        int s0 = t * 32;
        int cnt = 0;
        #pragma unroll
        for (int i = 0; i < 32; i++) cnt += (tokens[b * SQ + s0 + i] == EOSV);
        int pre = cnt;
        #pragma unroll
        for (int m = 1; m < 32; m <<= 1) {
            int v = __shfl_up_sync(0xffffffffu, pre, m);
            if (t >= m) pre += v;
        }
        pre -= cnt;
        int k = pre;
        #pragma unroll
        for (int i = 0; i < 32; i++) {
            int s = s0 + i;
            bool e = (tokens[b * SQ + s] == EOSV);
            g_dest[s * BS + b] = (e && k < NEOS) ? k : -1;
            k += e;
        }
    }

    // ---- GEMM: 128x128 tile, 16-k steps, 8x8 microtile, f32x2 ----
    __shared__ float A_sT[16 * 132];
    __shared__ float B_sT[16 * 132];

    int tid = threadIdx.x;
    int tx = tid & 15, ty = tid >> 4;
    int g0 = blockIdx.x * 128;
    int t0 = blockIdx.y * 128;

    u64 acc[8][4];
    #pragma unroll
    for (int i = 0; i < 8; i++)
        #pragma unroll
        for (int j = 0; j < 4; j++) acc[i][j] = 0ull;

    for (int k0 = 0; k0 < ED; k0 += 16) {
        __syncthreads();
        #pragma unroll
        for (int i = 0; i < 2; i++) {
            int ff  = tid + i * 256;
            int row = ff >> 2;
            int c4  = (ff & 3) * 4;
            float4 va = *(const float4*)&emb[(size_t)(t0 + row) * ED + k0 + c4];
            A_sT[(c4 + 0) * 132 + row] = va.x;
            A_sT[(c4 + 1) * 132 + row] = va.y;
            A_sT[(c4 + 2) * 132 + row] = va.z;
            A_sT[(c4 + 3) * 132 + row] = va.w;
            float4 vb = *(const float4*)&w_ih[(size_t)(g0 + row) * ED + k0 + c4];
            B_sT[(c4 + 0) * 132 + row] = vb.x;
            B_sT[(c4 + 1) * 132 + row] = vb.y;
            B_sT[(c4 + 2) * 132 + row] = vb.z;
            B_sT[(c4 + 3) * 132 + row] = vb.w;
        }
        __syncthreads();
        #pragma unroll
        for (int k = 0; k < 16; k++) {
            float4 a0 = *(const float4*)&A_sT[k * 132 + ty * 4];
            float4 a1 = *(const float4*)&A_sT[k * 132 + 64 + ty * 4];
            u64 b0x = *(const u64*)&B_sT[k * 132 + tx * 4];
            u64 b0y = *(const u64*)&B_sT[k * 132 + tx * 4 + 2];
            u64 b1x = *(const u64*)&B_sT[k * 132 + 64 + tx * 4];
            u64 b1y = *(const u64*)&B_sT[k * 132 + 64 + tx * 4 + 2];
            float af[8] = {a0.x, a0.y, a0.z, a0.w, a1.x, a1.y, a1.z, a1.w};
            #pragma unroll
            for (int i = 0; i < 8; i++) {
                u64 ap = bcast2(af[i]);
                acc[i][0] = ffma2(ap, b0x, acc[i][0]);
                acc[i][1] = ffma2(ap, b0y, acc[i][1]);
                acc[i][2] = ffma2(ap, b1x, acc[i][2]);
                acc[i][3] = ffma2(ap, b1y, acc[i][3]);
            }
        }
    }

    float4 bia0 = *(const float4*)&b_ih[g0 + tx * 4];
    float4 bia1 = *(const float4*)&b_ih[g0 + 64 + tx * 4];
    #pragma unroll
    for (int i = 0; i < 8; i++) {
        int trow = t0 + (i >> 2) * 64 + ty * 4 + (i & 3);
        float2 c0 = unpack2(acc[i][0]);
        float2 c1 = unpack2(acc[i][1]);
        float2 c2 = unpack2(acc[i][2]);
        float2 c3 = unpack2(acc[i][3]);
        float4 o0 = make_float4(c0.x + bia0.x, c0.y + bia0.y, c1.x + bia0.z, c1.y + bia0.w);
        float4 o1 = make_float4(c2.x + bia1.x, c2.y + bia1.y, c3.x + bia1.z, c3.y + bia1.w);
        *(float4*)&g_Gtab[(size_t)trow * G3 + g0 + tx * 4]      = o0;
        *(float4*)&g_Gtab[(size_t)trow * G3 + g0 + 64 + tx * 4] = o1;
    }
}

// ------------------- persistent GRU recurrence ------------------------------
// 256 threads/CTA, 128 CTAs in 16 clusters of 8 (same-bg clusters).
// bg = bid>>5, rg = bid&31, rank = bid&7.
// h(s) delivered by TMA multicast cooperative slicing: each CTA loads 4KB of
// the bg's 32KB tile and multicasts to all 8 cluster CTAs -> 8x less L2 read.
// Compute layout = R4: ks = tid>>4 (32-elem K slice), jl = tid&15 broadcast.
__global__ void __launch_bounds__(256, 1) __cluster_dims__(CLU, 1, 1)
gru_kernel(
    const __grid_constant__ CUtensorMap tmap,
    const int*   __restrict__ tokens,
    const float* __restrict__ w_hh,
    const float* __restrict__ b_hh,
    float*       __restrict__ out)
{
    extern __shared__ float sm[];
    float (*h_s)[HD] = (float(*)[HD])sm;                 // [16][512]  32KB (TMA dest)
    float* psum = sm + 16 * HD;                           // [16][16][PSTR]
    unsigned long long* mbar =
        (unsigned long long*)((char*)sm + SM_H_BYTES + SM_PSUM_BYTES);

    int tid = threadIdx.x;
    int bid = blockIdx.x;
    int bg = bid >> 5, rg = bid & 31;
    int rank = bid & (CLU - 1);
    int ks = tid >> 4;          // 0..15 (32-elem k slice)
    int jl = tid & 15;          // broadcast lanes
    int jG1 = rg * 16 + jl;

    unsigned mbar_a = smem_u32(mbar);
    unsigned hs_a   = smem_u32(sm);

    // one-time W_hh register load, rotated float4 order (matches h reads)
    u64 wr[16], wz[16], wn[16];
    #pragma unroll
    for (int i4 = 0; i4 < 8; i4++) {
        int col = ks * 32 + ((i4 + ks) & 7) * 4;
        const float* r0 = &w_hh[(size_t)(0 * HD + jG1) * HD + col];
        const float* r1 = &w_hh[(size_t)(1 * HD + jG1) * HD + col];
        const float* r2 = &w_hh[(size_t)(2 * HD + jG1) * HD + col];
        wr[2 * i4] = *(const u64*)r0;  wr[2 * i4 + 1] = *(const u64*)(r0 + 2);
        wz[2 * i4] = *(const u64*)r1;  wz[2 * i4 + 1] = *(const u64*)(r1 + 2);
        wn[2 * i4] = *(const u64*)r2;  wn[2 * i4 + 1] = *(const u64*)(r2 + 2);
    }

    // phase-2 / prefetch role
    int bl2 = tid >> 4, j2 = tid & 15;
    int bG2 = bg * 16 + bl2;
    int jG2 = rg * 16 + j2;
    float bhr = b_hh[jG2], bhz = b_hh[HD + jG2], bhn = b_hh[2 * HD + jG2];

    int tok0 = __ldg(&tokens[bG2 * SQ]);
    const float* gp0 = &g_Gtab[(size_t)tok0 * G3 + jG2];
    float pr = __ldcs(gp0), pz = __ldcs(gp0 + HD), pn = __ldcs(gp0 + 2 * HD);
    int pd = __ldg(&g_dest[bG2]);

    bool store_lane = ((ks & 1) == 0);
    int  slot = ks >> 1;                      // 0..7

    // ---- mbarrier init + cluster sync (peers' barriers must exist first) ----
    if (tid == 0) {
        asm volatile("mbarrier.init.shared.b64 [%0], %1;"
                     :: "r"(mbar_a), "r"(1u) : "memory");
    }
    __syncthreads();
    asm volatile("barrier.cluster.arrive.aligned;" ::: "memory");
    asm volatile("barrier.cluster.wait.aligned;"   ::: "memory");

    for (int s = 0; s < SQ; s++) {
        // ---- TMA multicast cooperative slice: h(s) -> all 8 cluster SMEMs ----
        if (tid == 0) {
            asm volatile("fence.proxy.async;" ::: "memory");
            asm volatile("mbarrier.arrive.expect_tx.shared.b64 _, [%0], %1;"
                         :: "r"(mbar_a), "r"((unsigned)H_TILE_BYTES) : "memory");
            int cy = bg * 32 + rank * SLICE_ROWS;
            int cz = s & 1;
            asm volatile(
                "cp.async.bulk.tensor.3d.shared::cluster.global.tile"
                ".mbarrier::complete_tx::bytes.multicast::cluster "
                "[%0], [%1, {%2, %3, %4}], [%5], %6;"
                :: "r"(hs_a + rank * SLICE_BYTES), "l"(&tmap),
                   "r"(0), "r"(cy), "r"(cz),
                   "r"(mbar_a), "h"((unsigned short)0xFF)
                : "memory");
        }
        // wait for full 32KB tile (8 slices) — phase parity = s&1
        {
            unsigned done;
            asm volatile(
                "{\n\t.reg .pred p;\n\t"
                "mbarrier.try_wait.parity.acquire.cta.shared::cta.b64 p, [%1], %2;\n\t"
                "selp.b32 %0, 1, 0, p;\n\t}"
                : "=r"(done) : "r"(mbar_a), "r"((unsigned)(s & 1)) : "memory");
            if (!done) {
                asm volatile(
                    "{\n\t.reg .pred P1;\n\t"
                    "WL_%=:\n\t"
                    "mbarrier.try_wait.parity.acquire.cta.shared::cta.b64 P1, [%0], %1, 0x989680;\n\t"
                    "@P1 bra.uni WD_%=;\n\t"
                    "bra.uni WL_%=;\n\t"
                    "WD_%=:\n\t}"
                    :: "r"(mbar_a), "r"((unsigned)(s & 1)) : "memory");
            }
        }

        // ---- phase 1: split-K partials, 2 batches at a time (6 chains) ----
        #pragma unroll 2
        for (int p = 0; p < 8; p++) {
            int b0 = 2 * p, b1 = 2 * p + 1;
            u64 a0r = 0, a0z = 0, a0n = 0, a1r = 0, a1z = 0, a1n = 0;
            #pragma unroll
            for (int i4 = 0; i4 < 8; i4++) {
                int col = ks * 32 + ((i4 + ks) & 7) * 4;
                ulonglong2 h0 = *(const ulonglong2*)&h_s[b0][col];
                ulonglong2 h1 = *(const ulonglong2*)&h_s[b1][col];
                a0r = ffma2(wr[2 * i4], h0.x, a0r);
                a1r = ffma2(wr[2 * i4], h1.x, a1r);
                a0z = ffma2(wz[2 * i4], h0.x, a0z);
                a1z = ffma2(wz[2 * i4], h1.x, a1z);
                a0n = ffma2(wn[2 * i4], h0.x, a0n);
                a1n = ffma2(wn[2 * i4], h1.x, a1n);
                a0r = ffma2(wr[2 * i4 + 1], h0.y, a0r);
                a1r = ffma2(wr[2 * i4 + 1], h1.y, a1r);
                a0z = ffma2(wz[2 * i4 + 1], h0.y, a0z);
                a1z = ffma2(wz[2 * i4 + 1], h1.y, a1z);
                a0n = ffma2(wn[2 * i4 + 1], h0.y, a0n);
                a1n = ffma2(wn[2 * i4 + 1], h1.y, a1n);
            }
            float v0r = hsum2(a0r), v0z = hsum2(a0z), v0n = hsum2(a0n);
            float v1r = hsum2(a1r), v1z = hsum2(a1z), v1n = hsum2(a1n);
            v0r += __shfl_xor_sync(0xffffffffu, v0r, 16);
            v0z += __shfl_xor_sync(0xffffffffu, v0z, 16);
            v0n += __shfl_xor_sync(0xffffffffu, v0n, 16);
            v1r += __shfl_xor_sync(0xffffffffu, v1r, 16);
            v1z += __shfl_xor_sync(0xffffffffu, v1z, 16);
            v1n += __shfl_xor_sync(0xffffffffu, v1n, 16);
            if (store_lane) {
                float* p0 = &psum[(b0 * 16 + jl) * PSTR];
                float* p1 = &psum[(b1 * 16 + jl) * PSTR];
                p0[slot] = v0r;  p0[8 + slot] = v0z;  p0[16 + slot] = v0n;
                p1[slot] = v1r;  p1[8 + slot] = v1z;  p1[16 + slot] = v1n;
            }
        }

        // ---- prefetch gi(s+1)/dest(s+1): latency hides under sync+barrier ----
        float nr = 0.f, nz = 0.f, nn2 = 0.f;
        int nd = -1;
        if (s + 1 < SQ) {
            int tk = __ldg(&tokens[bG2 * SQ + s + 1]);
            const float* gq = &g_Gtab[(size_t)tk * G3 + jG2];
            nr  = __ldcs(gq);
            nz  = __ldcs(gq + HD);
            nn2 = __ldcs(gq + 2 * HD);
            nd  = __ldg(&g_dest[(s + 1) * BS + bG2]);
        }
        __syncthreads();

        // ---- phase 2: reduce 8 slots per gate, gates, store ----
        {
            const float* pp = &psum[(bl2 * 16 + j2) * PSTR];
            float2 q0 = *(const float2*)&pp[0],  q1 = *(const float2*)&pp[2];
            float2 q2 = *(const float2*)&pp[4],  q3 = *(const float2*)&pp[6];
            float2 q4 = *(const float2*)&pp[8],  q5 = *(const float2*)&pp[10];
            float2 q6 = *(const float2*)&pp[12], q7 = *(const float2*)&pp[14];
            float2 q8 = *(const float2*)&pp[16], q9 = *(const float2*)&pp[18];
            float2 qa = *(const float2*)&pp[20], qb = *(const float2*)&pp[22];
            float rsum = ((q0.x + q0.y) + (q1.x + q1.y)) + ((q2.x + q2.y) + (q3.x + q3.y));
            float zsum = ((q4.x + q4.y) + (q5.x + q5.y)) + ((q6.x + q6.y) + (q7.x + q7.y));
            float nsum = ((q8.x + q8.y) + (q9.x + q9.y)) + ((qa.x + qa.y) + (qb.x + qb.y));
            float hprev = h_s[bl2][jG2];

            float r  = 1.f / (1.f + __expf(-(pr + rsum + bhr)));
            float z  = 1.f / (1.f + __expf(-(pz + zsum + bhz)));
            float nx = pn + r * (nsum + bhn);
            float e2 = __expf(-2.f * nx);
            float n  = 2.f / (1.f + e2) - 1.f;          // tanh, inf-safe
            float hnew = fmaf(z, hprev - n, n);         // (1-z)*n + z*h

            g_h[(s + 1) & 1][bG2 * HD + jG2] = hnew;
            if (pd >= 0) out[((size_t)pd * BS + bG2) * HD + jG2] = hnew;
            pr = nr; pz = nz; pn = nn2; pd = nd;
        }

        // ---- per-batch-group barrier (32 CTAs), tid0 poll + wake ----
        if (s + 1 < SQ) {
            __syncthreads();                    // orders h smem reads + stores
            if (tid == 0) {
                red_release_add(&g_ctr[bg * 64], 1u);
                unsigned tgt = 32u * (unsigned)(s + 1);
                while (ld_acq(&g_ctr[bg * 64]) < tgt) { }
            }
            __syncthreads();
        }
    }

    // hygiene: no CTA exits while peer multicast could still target its smem
    asm volatile("barrier.cluster.arrive.aligned;" ::: "memory");
    asm volatile("barrier.cluster.wait.aligned;"   ::: "memory");
}

// ------------------- launch -------------------------------------------------
typedef CUresult (*EncodeTiledFn)(
    CUtensorMap*, CUtensorMapDataType, cuuint32_t, void*,
    const cuuint64_t*, const cuuint64_t*, const cuuint32_t*, const cuuint32_t*,
    CUtensorMapInterleave, CUtensorMapSwizzle, CUtensorMapL2promotion,
    CUtensorMapFloatOOBfill);

extern "C" void kernel_launch(void* const* d_in, const int* in_sizes, int n_in,
                              void* d_out, int out_size) {
    const int*   tokens = (const int*)d_in[0];
    const float* emb    = (const float*)d_in[1];
    const float* w_ih   = (const float*)d_in[2];
    const float* w_hh   = (const float*)d_in[3];
    const float* b_ih   = (const float*)d_in[4];
    const float* b_hh   = (const float*)d_in[5];
    float* out = (float*)d_out;

    // Build tensormap for g_h viewed as [2][128 rows][256 f32] (row = 1KB)
    void* hptr = nullptr;
    cudaGetSymbolAddress(&hptr, g_h);
    EncodeTiledFn encode = nullptr;
    cudaDriverEntryPointQueryResult qr;
    cudaGetDriverEntryPoint("cuTensorMapEncodeTiled", (void**)&encode,
                            cudaEnableDefault, &qr);
    CUtensorMap tmap;
    {
        cuuint64_t dims[3]    = {256, 128, 2};
        cuuint64_t strides[2] = {256 * 4, (cuuint64_t)BS * HD * 4};
        cuuint32_t box[3]     = {256, SLICE_ROWS, 1};
        cuuint32_t estr[3]    = {1, 1, 1};
        encode(&tmap, CU_TENSOR_MAP_DATA_TYPE_FLOAT32, 3, hptr,
               dims, strides, box, estr,
               CU_TENSOR_MAP_INTERLEAVE_NONE, CU_TENSOR_MAP_SWIZZLE_NONE,
               CU_TENSOR_MAP_L2_PROMOTION_L2_128B,
               CU_TENSOR_MAP_FLOAT_OOB_FILL_NONE);
    }

    cudaFuncSetAttribute(gru_kernel,
                         cudaFuncAttributeMaxDynamicSharedMemorySize, GRU_SMEM);

    gtab_kernel<<<dim3(G3 / 128, VB / 128), 256>>>(emb, w_ih, b_ih, tokens);
    gru_kernel<<<NCTA, 256, GRU_SMEM>>>(tmap, tokens, w_hh, b_hh, out);
}

// round 10
// speedup vs baseline: 2.2729x; 2.2729x over previous
#include <cuda_runtime.h>

#define SQ   1024
#define BS   64
#define HD   512
#define ED   256
#define VB   32000
#define G3   1536
#define EOSV 2
#define NEOS 32

#define NBG  8            // batch groups (8 rows each)
#define NRG  32           // j groups (16 h-dims each)
#define NCTA (NBG*NRG)    // 256 CTAs, 2 per SM (stall overlap across bgs)

#define PSTR 14           // psum row stride (floats), 12 used
// dyn smem per CTA: h tile 16KB + psum 7KB
#define SM_H      (8*HD)
#define SM_PSUM   (8*16*PSTR)
#define GRU_SMEM  ((SM_H + SM_PSUM) * 4)

typedef unsigned long long u64;

// ------------------- device scratch (static only; no allocs) ----------------
__device__ float    g_Gtab[(size_t)VB * G3];   // ~197MB input-projection table
__device__ float    g_h[2][BS * HD];           // double-buffered hidden state
__device__ int      g_dest[SQ * BS];           // EOS compaction slot or -1
__device__ unsigned g_ctr[NBG * 64];           // barrier counters, 256B stride

// ------------------- packed f32x2 helpers ----------------------------------
__device__ __forceinline__ u64 ffma2(u64 a, u64 b, u64 c) {
    u64 d;
    asm("fma.rn.f32x2 %0, %1, %2, %3;" : "=l"(d) : "l"(a), "l"(b), "l"(c));
    return d;
}
__device__ __forceinline__ float2 unpack2(u64 v) {
    float2 f;
    asm("mov.b64 {%0, %1}, %2;" : "=f"(f.x), "=f"(f.y) : "l"(v));
    return f;
}
__device__ __forceinline__ float hsum2(u64 v) {
    float2 f = unpack2(v);
    return f.x + f.y;
}
__device__ __forceinline__ u64 bcast2(float x) {
    u64 d;
    asm("mov.b64 %0, {%1, %1};" : "=l"(d) : "f"(x));
    return d;
}
__device__ __forceinline__ unsigned ld_acq(const unsigned* p) {
    unsigned v;
    asm volatile("ld.acquire.gpu.global.u32 %0, [%1];" : "=r"(v) : "l"(p));
    return v;
}
__device__ __forceinline__ void red_release_add(unsigned* p, unsigned v) {
    asm volatile("red.release.gpu.global.add.u32 [%0], %1;" :: "l"(p), "r"(v) : "memory");
}

// ------------------- Gtab GEMM (+fused prep): G = w_ih * emb^T + b_ih ------
__global__ void __launch_bounds__(256) gtab_kernel(
    const float* __restrict__ emb,
    const float* __restrict__ w_ih,
    const float* __restrict__ b_ih,
    const int*   __restrict__ tokens)
{
    // ---- fused prep: h0, counters, EOS scan (first 64 flat CTAs, warp 0) ----
    int fid = blockIdx.y * 12 + blockIdx.x;
    if (fid < BS && threadIdx.x < 32) {
        int b = fid, t = threadIdx.x;
        if (fid == 0 && t < NBG) g_ctr[t * 64] = 0u;
        for (int i = t; i < HD; i += 32) g_h[0][b * HD + i] = 0.f;
        int s0 = t * 32;
        int cnt = 0;
        #pragma unroll
        for (int i = 0; i < 32; i++) cnt += (tokens[b * SQ + s0 + i] == EOSV);
        int pre = cnt;
        #pragma unroll
        for (int m = 1; m < 32; m <<= 1) {
            int v = __shfl_up_sync(0xffffffffu, pre, m);
            if (t >= m) pre += v;
        }
        pre -= cnt;
        int k = pre;
        #pragma unroll
        for (int i = 0; i < 32; i++) {
            int s = s0 + i;
            bool e = (tokens[b * SQ + s] == EOSV);
            g_dest[s * BS + b] = (e && k < NEOS) ? k : -1;
            k += e;
        }
    }

    // ---- GEMM: 128x128 tile, 16-k steps, 8x8 microtile, f32x2 ----
    __shared__ float A_sT[16 * 132];
    __shared__ float B_sT[16 * 132];

    int tid = threadIdx.x;
    int tx = tid & 15, ty = tid >> 4;
    int g0 = blockIdx.x * 128;
    int t0 = blockIdx.y * 128;

    u64 acc[8][4];
    #pragma unroll
    for (int i = 0; i < 8; i++)
        #pragma unroll
        for (int j = 0; j < 4; j++) acc[i][j] = 0ull;

    for (int k0 = 0; k0 < ED; k0 += 16) {
        __syncthreads();
        #pragma unroll
        for (int i = 0; i < 2; i++) {
            int ff  = tid + i * 256;
            int row = ff >> 2;
            int c4  = (ff & 3) * 4;
            float4 va = *(const float4*)&emb[(size_t)(t0 + row) * ED + k0 + c4];
            A_sT[(c4 + 0) * 132 + row] = va.x;
            A_sT[(c4 + 1) * 132 + row] = va.y;
            A_sT[(c4 + 2) * 132 + row] = va.z;
            A_sT[(c4 + 3) * 132 + row] = va.w;
            float4 vb = *(const float4*)&w_ih[(size_t)(g0 + row) * ED + k0 + c4];
            B_sT[(c4 + 0) * 132 + row] = vb.x;
            B_sT[(c4 + 1) * 132 + row] = vb.y;
            B_sT[(c4 + 2) * 132 + row] = vb.z;
            B_sT[(c4 + 3) * 132 + row] = vb.w;
        }
        __syncthreads();
        #pragma unroll
        for (int k = 0; k < 16; k++) {
            float4 a0 = *(const float4*)&A_sT[k * 132 + ty * 4];
            float4 a1 = *(const float4*)&A_sT[k * 132 + 64 + ty * 4];
            u64 b0x = *(const u64*)&B_sT[k * 132 + tx * 4];
            u64 b0y = *(const u64*)&B_sT[k * 132 + tx * 4 + 2];
            u64 b1x = *(const u64*)&B_sT[k * 132 + 64 + tx * 4];
            u64 b1y = *(const u64*)&B_sT[k * 132 + 64 + tx * 4 + 2];
            float af[8] = {a0.x, a0.y, a0.z, a0.w, a1.x, a1.y, a1.z, a1.w};
            #pragma unroll
            for (int i = 0; i < 8; i++) {
                u64 ap = bcast2(af[i]);
                acc[i][0] = ffma2(ap, b0x, acc[i][0]);
                acc[i][1] = ffma2(ap, b0y, acc[i][1]);
                acc[i][2] = ffma2(ap, b1x, acc[i][2]);
                acc[i][3] = ffma2(ap, b1y, acc[i][3]);
            }
        }
    }

    float4 bia0 = *(const float4*)&b_ih[g0 + tx * 4];
    float4 bia1 = *(const float4*)&b_ih[g0 + 64 + tx * 4];
    #pragma unroll
    for (int i = 0; i < 8; i++) {
        int trow = t0 + (i >> 2) * 64 + ty * 4 + (i & 3);
        float2 c0 = unpack2(acc[i][0]);
        float2 c1 = unpack2(acc[i][1]);
        float2 c2 = unpack2(acc[i][2]);
        float2 c3 = unpack2(acc[i][3]);
        float4 o0 = make_float4(c0.x + bia0.x, c0.y + bia0.y, c1.x + bia0.z, c1.y + bia0.w);
        float4 o1 = make_float4(c2.x + bia1.x, c2.y + bia1.y, c3.x + bia1.z, c3.y + bia1.w);
        *(float4*)&g_Gtab[(size_t)trow * G3 + g0 + tx * 4]      = o0;
        *(float4*)&g_Gtab[(size_t)trow * G3 + g0 + 64 + tx * 4] = o1;
    }
}

// ------------------- persistent GRU recurrence ------------------------------
// 256 CTAs (8 bg x 32 rg), 128 threads, 2 CTAs/SM. Co-resident CTAs serve
// DIFFERENT batch groups -> independent barriers -> the synchronized
// barrier/h-load stall of one CTA is hidden by the other's compute.
// Thread (ks=tid>>4 in 0..7: 64-elem K slice; jl=tid&15: broadcast lanes).
// W_hh slice in 96 u64 regs. Rotated columns keep warp's 2 ks regions on
// disjoint bank halves. shfl_xor(16) pairs ks -> 4 psum slots per gate.
__global__ void __launch_bounds__(128, 2) gru_kernel(
    const int*   __restrict__ tokens,
    const float* __restrict__ w_hh,
    const float* __restrict__ b_hh,
    float*       __restrict__ out)
{
    extern __shared__ float sm[];
    float (*h_s)[HD] = (float(*)[HD])sm;      // [8][512]  16KB
    float* psum = sm + SM_H;                   // [8*16][PSTR]

    int tid = threadIdx.x;
    int bid = blockIdx.x;
    int bg = bid >> 5, rg = bid & 31;
    int ks = tid >> 4;          // 0..7   (64-elem k slice)
    int jl = tid & 15;          // broadcast lanes
    int jG = rg * 16 + jl;

    // one-time W_hh register slice: 3 gates x 64 elems, rotated float4 order
    u64 wr[32], wz[32], wn[32];
    #pragma unroll
    for (int i4 = 0; i4 < 16; i4++) {
        int col = ks * 64 + ((i4 + 4 * ks) & 15) * 4;
        const float* r0 = &w_hh[(size_t)(0 * HD + jG) * HD + col];
        const float* r1 = &w_hh[(size_t)(1 * HD + jG) * HD + col];
        const float* r2 = &w_hh[(size_t)(2 * HD + jG) * HD + col];
        wr[2 * i4] = *(const u64*)r0;  wr[2 * i4 + 1] = *(const u64*)(r0 + 2);
        wz[2 * i4] = *(const u64*)r1;  wz[2 * i4 + 1] = *(const u64*)(r1 + 2);
        wn[2 * i4] = *(const u64*)r2;  wn[2 * i4 + 1] = *(const u64*)(r2 + 2);
    }

    // phase-2 / prefetch role: one (batch, j) per thread
    int bl2 = tid >> 4;                       // 0..7
    int bG2 = bg * 8 + bl2;
    int jG2 = jG;
    float bhr = b_hh[jG2], bhz = b_hh[HD + jG2], bhn = b_hh[2 * HD + jG2];

    int tok0 = __ldg(&tokens[bG2 * SQ]);
    const float* gp0 = &g_Gtab[(size_t)tok0 * G3 + jG2];
    float pr = __ldcs(gp0), pz = __ldcs(gp0 + HD), pn = __ldcs(gp0 + 2 * HD);
    int pd = __ldg(&g_dest[bG2]);

    bool store_lane = ((ks & 1) == 0);
    int  slot = ks >> 1;                      // 0..3

    for (int s = 0; s < SQ; s++) {
        // ---- load h(s): 8 rows x 512 = 1024 float4 -> 8 per thread ----
        {
            const float* hsrc = &g_h[s & 1][bg * 8 * HD];
            float4 hv[8];
            #pragma unroll
            for (int i = 0; i < 8; i++) {
                int f = tid + i * 128;
                hv[i] = __ldcg((const float4*)&hsrc[(f >> 7) * HD + (f & 127) * 4]);
            }
            #pragma unroll
            for (int i = 0; i < 8; i++) {
                int f = tid + i * 128;
                *(float4*)&h_s[f >> 7][(f & 127) * 4] = hv[i];
            }
        }
        __syncthreads();

        // ---- phase 1: split-K partials, 2 batches per pass (6 chains) ----
        #pragma unroll 2
        for (int p = 0; p < 4; p++) {
            int b0 = 2 * p, b1 = 2 * p + 1;
            u64 a0r = 0, a0z = 0, a0n = 0, a1r = 0, a1z = 0, a1n = 0;
            #pragma unroll
            for (int i4 = 0; i4 < 16; i4++) {
                int col = ks * 64 + ((i4 + 4 * ks) & 15) * 4;
                ulonglong2 h0 = *(const ulonglong2*)&h_s[b0][col];
                ulonglong2 h1 = *(const ulonglong2*)&h_s[b1][col];
                a0r = ffma2(wr[2 * i4], h0.x, a0r);
                a1r = ffma2(wr[2 * i4], h1.x, a1r);
                a0z = ffma2(wz[2 * i4], h0.x, a0z);
                a1z = ffma2(wz[2 * i4], h1.x, a1z);
                a0n = ffma2(wn[2 * i4], h0.x, a0n);
                a1n = ffma2(wn[2 * i4], h1.x, a1n);
                a0r = ffma2(wr[2 * i4 + 1], h0.y, a0r);
                a1r = ffma2(wr[2 * i4 + 1], h1.y, a1r);
                a0z = ffma2(wz[2 * i4 + 1], h0.y, a0z);
                a1z = ffma2(wz[2 * i4 + 1], h1.y, a1z);
                a0n = ffma2(wn[2 * i4 + 1], h0.y, a0n);
                a1n = ffma2(wn[2 * i4 + 1], h1.y, a1n);
            }
            float v0r = hsum2(a0r), v0z = hsum2(a0z), v0n = hsum2(a0n);
            float v1r = hsum2(a1r), v1z = hsum2(a1z), v1n = hsum2(a1n);
            // combine ks-pair (same jl, lane^16)
            v0r += __shfl_xor_sync(0xffffffffu, v0r, 16);
            v0z += __shfl_xor_sync(0xffffffffu, v0z, 16);
            v0n += __shfl_xor_sync(0xffffffffu, v0n, 16);
            v1r += __shfl_xor_sync(0xffffffffu, v1r, 16);
            v1z += __shfl_xor_sync(0xffffffffu, v1z, 16);
            v1n += __shfl_xor_sync(0xffffffffu, v1n, 16);
            if (store_lane) {
                float* p0 = &psum[(b0 * 16 + jl) * PSTR];
                float* p1 = &psum[(b1 * 16 + jl) * PSTR];
                p0[slot] = v0r;  p0[4 + slot] = v0z;  p0[8 + slot] = v0n;
                p1[slot] = v1r;  p1[4 + slot] = v1z;  p1[8 + slot] = v1n;
            }
        }

        // ---- prefetch gi(s+1)/dest(s+1): hidden under sync + next barrier ----
        float nr = 0.f, nz = 0.f, nn2 = 0.f;
        int nd = -1;
        if (s + 1 < SQ) {
            int tk = __ldg(&tokens[bG2 * SQ + s + 1]);
            const float* gq = &g_Gtab[(size_t)tk * G3 + jG2];
            nr  = __ldcs(gq);
            nz  = __ldcs(gq + HD);
            nn2 = __ldcs(gq + 2 * HD);
            nd  = __ldg(&g_dest[(s + 1) * BS + bG2]);
        }
        __syncthreads();

        // ---- phase 2: reduce 4 slots per gate, gates, store ----
        {
            const float* pp = &psum[tid * PSTR];
            float2 q0 = *(const float2*)&pp[0], q1 = *(const float2*)&pp[2];
            float2 q2 = *(const float2*)&pp[4], q3 = *(const float2*)&pp[6];
            float2 q4 = *(const float2*)&pp[8], q5 = *(const float2*)&pp[10];
            float rsum = (q0.x + q0.y) + (q1.x + q1.y);
            float zsum = (q2.x + q2.y) + (q3.x + q3.y);
            float nsum = (q4.x + q4.y) + (q5.x + q5.y);
            float hprev = h_s[bl2][jG2];

            float r  = 1.f / (1.f + __expf(-(pr + rsum + bhr)));
            float z  = 1.f / (1.f + __expf(-(pz + zsum + bhz)));
            float nx = pn + r * (nsum + bhn);
            float e2 = __expf(-2.f * nx);
            float n  = 2.f / (1.f + e2) - 1.f;          // tanh, inf-safe
            float hnew = fmaf(z, hprev - n, n);         // (1-z)*n + z*h

            g_h[(s + 1) & 1][bG2 * HD + jG2] = hnew;
            if (pd >= 0) out[((size_t)pd * BS + bG2) * HD + jG2] = hnew;
            pr = nr; pz = nz; pn = nn2; pd = nd;
        }

        // ---- per-batch-group barrier (32 CTAs), tid0 poll + wake ----
        if (s + 1 < SQ) {
            __syncthreads();                    // orders h stores before release
            if (tid == 0) {
                red_release_add(&g_ctr[bg * 64], 1u);
                unsigned tgt = 32u * (unsigned)(s + 1);
                while (ld_acq(&g_ctr[bg * 64]) < tgt) { }
            }
            __syncthreads();
        }
    }
}

// ------------------- launch -------------------------------------------------
extern "C" void kernel_launch(void* const* d_in, const int* in_sizes, int n_in,
                              void* d_out, int out_size) {
    const int*   tokens = (const int*)d_in[0];
    const float* emb    = (const float*)d_in[1];
    const float* w_ih   = (const float*)d_in[2];
    const float* w_hh   = (const float*)d_in[3];
    const float* b_ih   = (const float*)d_in[4];
    const float* b_hh   = (const float*)d_in[5];
    float* out = (float*)d_out;

    cudaFuncSetAttribute(gru_kernel,
                         cudaFuncAttributeMaxDynamicSharedMemorySize, GRU_SMEM);

    gtab_kernel<<<dim3(G3 / 128, VB / 128), 256>>>(emb, w_ih, b_ih, tokens);
    gru_kernel<<<NCTA, 128, GRU_SMEM>>>(tokens, w_hh, b_hh, out);
}

// round 11
// speedup vs baseline: 2.3215x; 1.0214x over previous
#include <cuda_runtime.h>

#define SQ   1024
#define BS   64
#define HD   512
#define ED   256
#define VB   32000
#define G3   1536
#define EOSV 2
#define NEOS 32

#define NBG  8            // batch groups (8 rows each)
#define NRG  32           // j groups (16 h-dims each)
#define NCTA (NBG*NRG)    // 256 CTAs, 2 per SM (stall overlap across bgs)

#define STAGGER_CYC 3000ull   // half-step head start for bgs 0-3

#define PSTR 14           // psum row stride (floats), 12 used
// dyn smem per CTA: h tile 16KB + psum 7KB
#define SM_H      (8*HD)
#define SM_PSUM   (8*16*PSTR)
#define GRU_SMEM  ((SM_H + SM_PSUM) * 4)

typedef unsigned long long u64;

// ------------------- device scratch (static only; no allocs) ----------------
__device__ float    g_Gtab[(size_t)VB * G3];   // ~197MB input-projection table
__device__ float    g_h[2][BS * HD];           // double-buffered hidden state
__device__ int      g_dest[SQ * BS];           // EOS compaction slot or -1
__device__ unsigned g_ctr[NBG * 64];           // barrier counters, 256B stride

// ------------------- packed f32x2 helpers ----------------------------------
__device__ __forceinline__ u64 ffma2(u64 a, u64 b, u64 c) {
    u64 d;
    asm("fma.rn.f32x2 %0, %1, %2, %3;" : "=l"(d) : "l"(a), "l"(b), "l"(c));
    return d;
}
__device__ __forceinline__ float2 unpack2(u64 v) {
    float2 f;
    asm("mov.b64 {%0, %1}, %2;" : "=f"(f.x), "=f"(f.y) : "l"(v));
    return f;
}
__device__ __forceinline__ float hsum2(u64 v) {
    float2 f = unpack2(v);
    return f.x + f.y;
}
__device__ __forceinline__ u64 bcast2(float x) {
    u64 d;
    asm("mov.b64 %0, {%1, %1};" : "=l"(d) : "f"(x));
    return d;
}
__device__ __forceinline__ unsigned ld_acq(const unsigned* p) {
    unsigned v;
    asm volatile("ld.acquire.gpu.global.u32 %0, [%1];" : "=r"(v) : "l"(p));
    return v;
}
__device__ __forceinline__ void red_release_add(unsigned* p, unsigned v) {
    asm volatile("red.release.gpu.global.add.u32 [%0], %1;" :: "l"(p), "r"(v) : "memory");
}

// ------------------- Gtab GEMM (+fused prep): G = w_ih * emb^T + b_ih ------
__global__ void __launch_bounds__(256) gtab_kernel(
    const float* __restrict__ emb,
    const float* __restrict__ w_ih,
    const float* __restrict__ b_ih,
    const int*   __restrict__ tokens)
{
    // ---- fused prep: h0, counters, EOS scan (first 64 flat CTAs, warp 0) ----
    int fid = blockIdx.y * 12 + blockIdx.x;
    if (fid < BS && threadIdx.x < 32) {
        int b = fid, t = threadIdx.x;
        if (fid == 0 && t < NBG) g_ctr[t * 64] = 0u;
        for (int i = t; i < HD; i += 32) g_h[0][b * HD + i] = 0.f;
        int s0 = t * 32;
        int cnt = 0;
        #pragma unroll
        for (int i = 0; i < 32; i++) cnt += (tokens[b * SQ + s0 + i] == EOSV);
        int pre = cnt;
        #pragma unroll
        for (int m = 1; m < 32; m <<= 1) {
            int v = __shfl_up_sync(0xffffffffu, pre, m);
            if (t >= m) pre += v;
        }
        pre -= cnt;
        int k = pre;
        #pragma unroll
        for (int i = 0; i < 32; i++) {
            int s = s0 + i;
            bool e = (tokens[b * SQ + s] == EOSV);
            g_dest[s * BS + b] = (e && k < NEOS) ? k : -1;
            k += e;
        }
    }

    // ---- GEMM: 128x128 tile, 16-k steps, 8x8 microtile, f32x2 ----
    __shared__ float A_sT[16 * 132];
    __shared__ float B_sT[16 * 132];

    int tid = threadIdx.x;
    int tx = tid & 15, ty = tid >> 4;
    int g0 = blockIdx.x * 128;
    int t0 = blockIdx.y * 128;

    u64 acc[8][4];
    #pragma unroll
    for (int i = 0; i < 8; i++)
        #pragma unroll
        for (int j = 0; j < 4; j++) acc[i][j] = 0ull;

    for (int k0 = 0; k0 < ED; k0 += 16) {
        __syncthreads();
        #pragma unroll
        for (int i = 0; i < 2; i++) {
            int ff  = tid + i * 256;
            int row = ff >> 2;
            int c4  = (ff & 3) * 4;
            float4 va = *(const float4*)&emb[(size_t)(t0 + row) * ED + k0 + c4];
            A_sT[(c4 + 0) * 132 + row] = va.x;
            A_sT[(c4 + 1) * 132 + row] = va.y;
            A_sT[(c4 + 2) * 132 + row] = va.z;
            A_sT[(c4 + 3) * 132 + row] = va.w;
            float4 vb = *(const float4*)&w_ih[(size_t)(g0 + row) * ED + k0 + c4];
            B_sT[(c4 + 0) * 132 + row] = vb.x;
            B_sT[(c4 + 1) * 132 + row] = vb.y;
            B_sT[(c4 + 2) * 132 + row] = vb.z;
            B_sT[(c4 + 3) * 132 + row] = vb.w;
        }
        __syncthreads();
        #pragma unroll
        for (int k = 0; k < 16; k++) {
            float4 a0 = *(const float4*)&A_sT[k * 132 + ty * 4];
            float4 a1 = *(const float4*)&A_sT[k * 132 + 64 + ty * 4];
            u64 b0x = *(const u64*)&B_sT[k * 132 + tx * 4];
            u64 b0y = *(const u64*)&B_sT[k * 132 + tx * 4 + 2];
            u64 b1x = *(const u64*)&B_sT[k * 132 + 64 + tx * 4];
            u64 b1y = *(const u64*)&B_sT[k * 132 + 64 + tx * 4 + 2];
            float af[8] = {a0.x, a0.y, a0.z, a0.w, a1.x, a1.y, a1.z, a1.w};
            #pragma unroll
            for (int i = 0; i < 8; i++) {
                u64 ap = bcast2(af[i]);
                acc[i][0] = ffma2(ap, b0x, acc[i][0]);
                acc[i][1] = ffma2(ap, b0y, acc[i][1]);
                acc[i][2] = ffma2(ap, b1x, acc[i][2]);
                acc[i][3] = ffma2(ap, b1y, acc[i][3]);
            }
        }
    }

    float4 bia0 = *(const float4*)&b_ih[g0 + tx * 4];
    float4 bia1 = *(const float4*)&b_ih[g0 + 64 + tx * 4];
    #pragma unroll
    for (int i = 0; i < 8; i++) {
        int trow = t0 + (i >> 2) * 64 + ty * 4 + (i & 3);
        float2 c0 = unpack2(acc[i][0]);
        float2 c1 = unpack2(acc[i][1]);
        float2 c2 = unpack2(acc[i][2]);
        float2 c3 = unpack2(acc[i][3]);
        float4 o0 = make_float4(c0.x + bia0.x, c0.y + bia0.y, c1.x + bia0.z, c1.y + bia0.w);
        float4 o1 = make_float4(c2.x + bia1.x, c2.y + bia1.y, c3.x + bia1.z, c3.y + bia1.w);
        *(float4*)&g_Gtab[(size_t)trow * G3 + g0 + tx * 4]      = o0;
        *(float4*)&g_Gtab[(size_t)trow * G3 + g0 + 64 + tx * 4] = o1;
    }
}

// ------------------- persistent GRU recurrence ------------------------------
// 256 CTAs (8 bg x 32 rg), 128 threads, 2 CTAs/SM. Co-resident CTAs serve
// DIFFERENT batch groups with independent barriers; bgs 4-7 are deliberately
// started ~half a step late so the paired CTAs run ANTI-PHASED: one CTA's
// barrier/h-load stall is covered by the other's compute window. Each bg's
// own barrier lockstep preserves the phase offset for all 1024 steps.
__global__ void __launch_bounds__(128, 2) gru_kernel(
    const int*   __restrict__ tokens,
    const float* __restrict__ w_hh,
    const float* __restrict__ b_hh,
    float*       __restrict__ out)
{
    extern __shared__ float sm[];
    float (*h_s)[HD] = (float(*)[HD])sm;      // [8][512]  16KB
    float* psum = sm + SM_H;                   // [8*16][PSTR]

    int tid = threadIdx.x;
    int bid = blockIdx.x;
    int bg = bid >> 5, rg = bid & 31;
    int ks = tid >> 4;          // 0..7   (64-elem k slice)
    int jl = tid & 15;          // broadcast lanes
    int jG = rg * 16 + jl;

    // one-time W_hh register slice: 3 gates x 64 elems, rotated float4 order
    u64 wr[32], wz[32], wn[32];
    #pragma unroll
    for (int i4 = 0; i4 < 16; i4++) {
        int col = ks * 64 + ((i4 + 4 * ks) & 15) * 4;
        const float* r0 = &w_hh[(size_t)(0 * HD + jG) * HD + col];
        const float* r1 = &w_hh[(size_t)(1 * HD + jG) * HD + col];
        const float* r2 = &w_hh[(size_t)(2 * HD + jG) * HD + col];
        wr[2 * i4] = *(const u64*)r0;  wr[2 * i4 + 1] = *(const u64*)(r0 + 2);
        wz[2 * i4] = *(const u64*)r1;  wz[2 * i4 + 1] = *(const u64*)(r1 + 2);
        wn[2 * i4] = *(const u64*)r2;  wn[2 * i4 + 1] = *(const u64*)(r2 + 2);
    }

    // phase-2 / prefetch role: one (batch, j) per thread
    int bl2 = tid >> 4;                       // 0..7
    int bG2 = bg * 8 + bl2;
    int jG2 = jG;
    float bhr = b_hh[jG2], bhz = b_hh[HD + jG2], bhn = b_hh[2 * HD + jG2];

    int tok0 = __ldg(&tokens[bG2 * SQ]);
    const float* gp0 = &g_Gtab[(size_t)tok0 * G3 + jG2];
    float pr = __ldcs(gp0), pz = __ldcs(gp0 + HD), pn = __ldcs(gp0 + 2 * HD);
    int pd = __ldg(&g_dest[bG2]);

    bool store_lane = ((ks & 1) == 0);
    int  slot = ks >> 1;                      // 0..3

    // ---- anti-phase stagger: bgs 4-7 start half a step late ----
    if (bg >= 4) {
        unsigned long long tc0 = clock64();
        while (clock64() - tc0 < STAGGER_CYC) { }
    }
    __syncthreads();

    for (int s = 0; s < SQ; s++) {
        // ---- load h(s): 8 rows x 512 = 1024 float4 -> 8 per thread ----
        {
            const float* hsrc = &g_h[s & 1][bg * 8 * HD];
            float4 hv[8];
            #pragma unroll
            for (int i = 0; i < 8; i++) {
                int f = tid + i * 128;
                hv[i] = __ldcg((const float4*)&hsrc[(f >> 7) * HD + (f & 127) * 4]);
            }
            #pragma unroll
            for (int i = 0; i < 8; i++) {
                int f = tid + i * 128;
                *(float4*)&h_s[f >> 7][(f & 127) * 4] = hv[i];
            }
        }
        __syncthreads();

        // ---- phase 1: split-K partials, 2 batches per pass (6 chains) ----
        #pragma unroll 2
        for (int p = 0; p < 4; p++) {
            int b0 = 2 * p, b1 = 2 * p + 1;
            u64 a0r = 0, a0z = 0, a0n = 0, a1r = 0, a1z = 0, a1n = 0;
            #pragma unroll
            for (int i4 = 0; i4 < 16; i4++) {
                int col = ks * 64 + ((i4 + 4 * ks) & 15) * 4;
                ulonglong2 h0 = *(const ulonglong2*)&h_s[b0][col];
                ulonglong2 h1 = *(const ulonglong2*)&h_s[b1][col];
                a0r = ffma2(wr[2 * i4], h0.x, a0r);
                a1r = ffma2(wr[2 * i4], h1.x, a1r);
                a0z = ffma2(wz[2 * i4], h0.x, a0z);
                a1z = ffma2(wz[2 * i4], h1.x, a1z);
                a0n = ffma2(wn[2 * i4], h0.x, a0n);
                a1n = ffma2(wn[2 * i4], h1.x, a1n);
                a0r = ffma2(wr[2 * i4 + 1], h0.y, a0r);
                a1r = ffma2(wr[2 * i4 + 1], h1.y, a1r);
                a0z = ffma2(wz[2 * i4 + 1], h0.y, a0z);
                a1z = ffma2(wz[2 * i4 + 1], h1.y, a1z);
                a0n = ffma2(wn[2 * i4 + 1], h0.y, a0n);
                a1n = ffma2(wn[2 * i4 + 1], h1.y, a1n);
            }
            float v0r = hsum2(a0r), v0z = hsum2(a0z), v0n = hsum2(a0n);
            float v1r = hsum2(a1r), v1z = hsum2(a1z), v1n = hsum2(a1n);
            // combine ks-pair (same jl, lane^16)
            v0r += __shfl_xor_sync(0xffffffffu, v0r, 16);
            v0z += __shfl_xor_sync(0xffffffffu, v0z, 16);
            v0n += __shfl_xor_sync(0xffffffffu, v0n, 16);
            v1r += __shfl_xor_sync(0xffffffffu, v1r, 16);
            v1z += __shfl_xor_sync(0xffffffffu, v1z, 16);
            v1n += __shfl_xor_sync(0xffffffffu, v1n, 16);
            if (store_lane) {
                float* p0 = &psum[(b0 * 16 + jl) * PSTR];
                float* p1 = &psum[(b1 * 16 + jl) * PSTR];
                p0[slot] = v0r;  p0[4 + slot] = v0z;  p0[8 + slot] = v0n;
                p1[slot] = v1r;  p1[4 + slot] = v1z;  p1[8 + slot] = v1n;
            }
        }

        // ---- prefetch gi(s+1)/dest(s+1): hidden under sync + next barrier ----
        float nr = 0.f, nz = 0.f, nn2 = 0.f;
        int nd = -1;
        if (s + 1 < SQ) {
            int tk = __ldg(&tokens[bG2 * SQ + s + 1]);
            const float* gq = &g_Gtab[(size_t)tk * G3 + jG2];
            nr  = __ldcs(gq);
            nz  = __ldcs(gq + HD);
            nn2 = __ldcs(gq + 2 * HD);
            nd  = __ldg(&g_dest[(s + 1) * BS + bG2]);
        }
        __syncthreads();

        // ---- phase 2: reduce 4 slots per gate, gates, store ----
        {
            const float* pp = &psum[tid * PSTR];
            float2 q0 = *(const float2*)&pp[0], q1 = *(const float2*)&pp[2];
            float2 q2 = *(const float2*)&pp[4], q3 = *(const float2*)&pp[6];
            float2 q4 = *(const float2*)&pp[8], q5 = *(const float2*)&pp[10];
            float rsum = (q0.x + q0.y) + (q1.x + q1.y);
            float zsum = (q2.x + q2.y) + (q3.x + q3.y);
            float nsum = (q4.x + q4.y) + (q5.x + q5.y);
            float hprev = h_s[bl2][jG2];

            float r  = 1.f / (1.f + __expf(-(pr + rsum + bhr)));
            float z  = 1.f / (1.f + __expf(-(pz + zsum + bhz)));
            float nx = pn + r * (nsum + bhn);
            float e2 = __expf(-2.f * nx);
            float n  = 2.f / (1.f + e2) - 1.f;          // tanh, inf-safe
            float hnew = fmaf(z, hprev - n, n);         // (1-z)*n + z*h

            g_h[(s + 1) & 1][bG2 * HD + jG2] = hnew;
            if (pd >= 0) out[((size_t)pd * BS + bG2) * HD + jG2] = hnew;
            pr = nr; pz = nz; pn = nn2; pd = nd;
        }

        // ---- per-batch-group barrier (32 CTAs), tid0 poll + wake ----
        if (s + 1 < SQ) {
            __syncthreads();                    // orders h stores before release
            if (tid == 0) {
                red_release_add(&g_ctr[bg * 64], 1u);
                unsigned tgt = 32u * (unsigned)(s + 1);
                while (ld_acq(&g_ctr[bg * 64]) < tgt) { }
            }
            __syncthreads();
        }
    }
}

// ------------------- launch -------------------------------------------------
extern "C" void kernel_launch(void* const* d_in, const int* in_sizes, int n_in,
                              void* d_out, int out_size) {
    const int*   tokens = (const int*)d_in[0];
    const float* emb    = (const float*)d_in[1];
    const float* w_ih   = (const float*)d_in[2];
    const float* w_hh   = (const float*)d_in[3];
    const float* b_ih   = (const float*)d_in[4];
    const float* b_hh   = (const float*)d_in[5];
    float* out = (float*)d_out;

    cudaFuncSetAttribute(gru_kernel,
                         cudaFuncAttributeMaxDynamicSharedMemorySize, GRU_SMEM);

    gtab_kernel<<<dim3(G3 / 128, VB / 128), 256>>>(emb, w_ih, b_ih, tokens);
    gru_kernel<<<NCTA, 128, GRU_SMEM>>>(tokens, w_hh, b_hh, out);
}